// round 1
// baseline (speedup 1.0000x reference)
#include <cuda_runtime.h>
#include <math.h>

// Problem constants (MiniGPT: B=4, T=1024, D=768, H=12, L=4, V=32000, HD=64)
#define BB 4
#define TT 1024
#define DD 768
#define HH 12
#define LL 4
#define VV 32000
#define HD 64
#define D4 (4*DD)

// ---------------------------------------------------------------------------
// Scratch (device globals — no allocations allowed)
// ---------------------------------------------------------------------------
__device__ float g_x[BB*TT*DD];      // residual stream
__device__ float g_h[BB*TT*DD];      // LN output
__device__ float g_q[BB*TT*DD];
__device__ float g_k[BB*TT*DD];
__device__ float g_v[BB*TT*DD];
__device__ float g_o[BB*TT*DD];      // attention output (pre-projection)
__device__ float g_s[(size_t)BB*HH*TT*TT];   // attention scores/probs (201 MB)
__device__ float g_m[(size_t)BB*TT*D4];      // MLP hidden (50 MB)

// ---------------------------------------------------------------------------
// Embedding: x[b,t,:] = tok_emb[idx[b,t],:] + pos_emb[t,:]
// ---------------------------------------------------------------------------
__global__ void embed_kernel(const int* __restrict__ idx,
                             const float* __restrict__ tok,
                             const float* __restrict__ pos,
                             float* __restrict__ x) {
    int i = blockIdx.x * blockDim.x + threadIdx.x;
    if (i >= BB*TT*DD) return;
    int d  = i % DD;
    int bt = i / DD;
    int t  = bt % TT;
    x[i] = tok[(size_t)idx[bt]*DD + d] + pos[(size_t)t*DD + d];
}

// ---------------------------------------------------------------------------
// LayerNorm over last dim (D=768). One block (256 threads) per row.
// ---------------------------------------------------------------------------
__global__ void ln_kernel(const float* __restrict__ in, float* __restrict__ out,
                          const float* __restrict__ gw, const float* __restrict__ bw) {
    int row = blockIdx.x;
    const float* x = in  + (size_t)row*DD;
    float*       y = out + (size_t)row*DD;
    int tid = threadIdx.x;

    float s = 0.f, s2 = 0.f;
    for (int i = tid; i < DD; i += 256) { float v = x[i]; s += v; s2 += v*v; }
    #pragma unroll
    for (int o = 16; o; o >>= 1) {
        s  += __shfl_xor_sync(0xffffffffu, s,  o);
        s2 += __shfl_xor_sync(0xffffffffu, s2, o);
    }
    __shared__ float r1[8], r2[8];
    __shared__ float smean, sinv;
    int w = tid >> 5;
    if ((tid & 31) == 0) { r1[w] = s; r2[w] = s2; }
    __syncthreads();
    if (tid == 0) {
        float a = 0.f, b2 = 0.f;
        #pragma unroll
        for (int i = 0; i < 8; i++) { a += r1[i]; b2 += r2[i]; }
        float mean = a / DD;
        float var  = b2 / DD - mean*mean;
        smean = mean;
        sinv  = rsqrtf(var + 1e-5f);
    }
    __syncthreads();
    float mean = smean, inv = sinv;
    for (int i = tid; i < DD; i += 256)
        y[i] = (x[i] - mean) * inv * gw[i] + bw[i];
}

// ---------------------------------------------------------------------------
// Generic tiled SGEMM: C = act(alpha * A@B + bias [+ resid])
//   A: [M,K] row-major (lda), batch stride sA
//   B: [K,N] row-major (ldb) or, if transB, stored [N,K] row-major (ldb)
//   C: [M,N] row-major (ldc), batch stride sC; resid shares ldc/sC.
//   causal: skip blocks entirely above the diagonal (scores GEMM).
// Tile: BM=128, BN=64, BK=16; 256 threads; 8x4 per-thread micro-tile.
// All dims assumed divisible by tile sizes (true for this problem).
// ---------------------------------------------------------------------------
#define GBM 128
#define GBN 64
#define GBK 16

__global__ __launch_bounds__(256)
void gemm_kernel(const float* __restrict__ A, int lda, long long sA,
                 const float* __restrict__ Bp, int ldb, long long sB, int transB,
                 float* __restrict__ C, int ldc, long long sC,
                 const float* __restrict__ bias,
                 const float* __restrict__ resid,
                 int K, float alpha, int relu, int causal) {
    int bz = blockIdx.z;
    A  += sA * bz;
    Bp += sB * bz;
    C  += sC * bz;
    if (resid) resid += sC * bz;

    int bm = blockIdx.y * GBM;
    int bn = blockIdx.x * GBN;
    if (causal && bn >= bm + GBM) return;   // fully masked block

    __shared__ float As[GBK][GBM];
    __shared__ float Bs[GBK][GBN];

    int tid = threadIdx.x;
    int tx = tid & 15;        // 0..15 -> 4 cols each
    int ty = tid >> 4;        // 0..15 -> 8 rows each

    float acc[8][4];
    #pragma unroll
    for (int i = 0; i < 8; i++)
        #pragma unroll
        for (int j = 0; j < 4; j++) acc[i][j] = 0.f;

    for (int k0 = 0; k0 < K; k0 += GBK) {
        // Load A tile: 128x16 = 512 float4, 2 per thread
        #pragma unroll
        for (int l = 0; l < 2; l++) {
            int e = tid + l * 256;
            int r = e >> 2, cq = e & 3;
            float4 av = *(const float4*)(A + (long long)(bm + r) * lda + k0 + cq*4);
            As[cq*4+0][r] = av.x;
            As[cq*4+1][r] = av.y;
            As[cq*4+2][r] = av.z;
            As[cq*4+3][r] = av.w;
        }
        // Load B tile: 16x64 = 256 float4, 1 per thread
        if (!transB) {
            int r = tid >> 4, cq = tid & 15;
            float4 bv = *(const float4*)(Bp + (long long)(k0 + r) * ldb + bn + cq*4);
            Bs[r][cq*4+0] = bv.x;
            Bs[r][cq*4+1] = bv.y;
            Bs[r][cq*4+2] = bv.z;
            Bs[r][cq*4+3] = bv.w;
        } else {
            int n = tid >> 2, eq = tid & 3;
            float4 bv = *(const float4*)(Bp + (long long)(bn + n) * ldb + k0 + eq*4);
            Bs[eq*4+0][n] = bv.x;
            Bs[eq*4+1][n] = bv.y;
            Bs[eq*4+2][n] = bv.z;
            Bs[eq*4+3][n] = bv.w;
        }
        __syncthreads();

        #pragma unroll
        for (int kk = 0; kk < GBK; kk++) {
            float a[8], b[4];
            #pragma unroll
            for (int i = 0; i < 8; i++) a[i] = As[kk][ty*8 + i];
            #pragma unroll
            for (int j = 0; j < 4; j++) b[j] = Bs[kk][tx*4 + j];
            #pragma unroll
            for (int i = 0; i < 8; i++)
                #pragma unroll
                for (int j = 0; j < 4; j++)
                    acc[i][j] = fmaf(a[i], b[j], acc[i][j]);
        }
        __syncthreads();
    }

    // Epilogue (float4 stores)
    int c0 = bn + tx*4;
    float4 bb = make_float4(0.f, 0.f, 0.f, 0.f);
    if (bias) bb = *(const float4*)(bias + c0);
    #pragma unroll
    for (int i = 0; i < 8; i++) {
        long long off = (long long)(bm + ty*8 + i) * ldc + c0;
        float4 v;
        v.x = acc[i][0]*alpha + bb.x;
        v.y = acc[i][1]*alpha + bb.y;
        v.z = acc[i][2]*alpha + bb.z;
        v.w = acc[i][3]*alpha + bb.w;
        if (resid) {
            float4 rr = *(const float4*)(resid + off);
            v.x += rr.x; v.y += rr.y; v.z += rr.z; v.w += rr.w;
        }
        if (relu) {
            v.x = fmaxf(v.x, 0.f); v.y = fmaxf(v.y, 0.f);
            v.z = fmaxf(v.z, 0.f); v.w = fmaxf(v.w, 0.f);
        }
        *(float4*)(C + off) = v;
    }
}

// ---------------------------------------------------------------------------
// Causal softmax over score rows. One block (128 threads) per (b,h,q) row.
// Masked tail is zeroed so the P@V GEMM can use full K=T.
// ---------------------------------------------------------------------------
__global__ void softmax_kernel(float* __restrict__ s) {
    long long row = blockIdx.x;
    int q = (int)(row % TT);
    float* p = s + row * (long long)TT;
    int n = q + 1;
    int tid = threadIdx.x;

    float m = -1e30f;
    for (int i = tid; i < n; i += 128) m = fmaxf(m, p[i]);
    #pragma unroll
    for (int o = 16; o; o >>= 1) m = fmaxf(m, __shfl_xor_sync(0xffffffffu, m, o));

    __shared__ float red[4];
    __shared__ float bm, bsum;
    if ((tid & 31) == 0) red[tid >> 5] = m;
    __syncthreads();
    if (tid == 0) {
        float v = red[0];
        #pragma unroll
        for (int i = 1; i < 4; i++) v = fmaxf(v, red[i]);
        bm = v;
    }
    __syncthreads();
    m = bm;

    float sum = 0.f;
    for (int i = tid; i < n; i += 128) {
        float e = expf(p[i] - m);
        p[i] = e;
        sum += e;
    }
    #pragma unroll
    for (int o = 16; o; o >>= 1) sum += __shfl_xor_sync(0xffffffffu, sum, o);
    __syncthreads();
    if ((tid & 31) == 0) red[tid >> 5] = sum;
    __syncthreads();
    if (tid == 0) {
        float v = 0.f;
        #pragma unroll
        for (int i = 0; i < 4; i++) v += red[i];
        bsum = v;
    }
    __syncthreads();
    float inv = 1.f / bsum;
    for (int i = tid; i < n; i += 128) p[i] *= inv;
    for (int i = n + tid; i < TT; i += 128) p[i] = 0.f;
}

// ---------------------------------------------------------------------------
// Host orchestration
// ---------------------------------------------------------------------------
extern "C" void kernel_launch(void* const* d_in, const int* in_sizes, int n_in,
                              void* d_out, int out_size) {
    const int*   idx    = (const int*)  d_in[0];
    const float* tok    = (const float*)d_in[1];
    const float* pos    = (const float*)d_in[2];
    const float* wq     = (const float*)d_in[3];
    const float* wk     = (const float*)d_in[4];
    const float* wv     = (const float*)d_in[5];
    const float* wo     = (const float*)d_in[6];
    const float* bo     = (const float*)d_in[7];
    const float* ln1_g  = (const float*)d_in[8];
    const float* ln1_b  = (const float*)d_in[9];
    const float* ln2_g  = (const float*)d_in[10];
    const float* ln2_b  = (const float*)d_in[11];
    const float* w1     = (const float*)d_in[12];
    const float* b1     = (const float*)d_in[13];
    const float* w2     = (const float*)d_in[14];
    const float* b2     = (const float*)d_in[15];
    const float* lnf_g  = (const float*)d_in[16];
    const float* lnf_b  = (const float*)d_in[17];
    const float* w_lm   = (const float*)d_in[18];
    const float* b_lm   = (const float*)d_in[19];

    float *x, *h, *q, *k, *v, *o, *s, *mbuf;
    cudaGetSymbolAddress((void**)&x,    g_x);
    cudaGetSymbolAddress((void**)&h,    g_h);
    cudaGetSymbolAddress((void**)&q,    g_q);
    cudaGetSymbolAddress((void**)&k,    g_k);
    cudaGetSymbolAddress((void**)&v,    g_v);
    cudaGetSymbolAddress((void**)&o,    g_o);
    cudaGetSymbolAddress((void**)&s,    g_s);
    cudaGetSymbolAddress((void**)&mbuf, g_m);

    const int ROWS = BB * TT;                  // 4096
    const float scale = 0.125f;                // HD^-0.5

    embed_kernel<<<(BB*TT*DD + 255)/256, 256>>>(idx, tok, pos, x);

    dim3 gProj(DD/GBN,  ROWS/GBM);             // (12, 32)
    dim3 gMlp1(D4/GBN,  ROWS/GBM);             // (48, 32)
    dim3 gScr (TT/GBN,  TT/GBM, HH);           // (16, 8, 12) per batch
    dim3 gPV  (HD/GBN,  TT/GBM, HH);           // (1, 8, 12)  per batch

    for (int l = 0; l < LL; l++) {
        const float* wq_l = wq + (size_t)l*DD*DD;
        const float* wk_l = wk + (size_t)l*DD*DD;
        const float* wv_l = wv + (size_t)l*DD*DD;
        const float* wo_l = wo + (size_t)l*DD*DD;
        const float* w1_l = w1 + (size_t)l*DD*D4;
        const float* w2_l = w2 + (size_t)l*D4*DD;

        // LN1
        ln_kernel<<<ROWS, 256>>>(x, h, ln1_g + l*DD, ln1_b + l*DD);

        // Q, K, V projections
        gemm_kernel<<<gProj, 256>>>(h, DD, 0, wq_l, DD, 0, 0, q, DD, 0,
                                    nullptr, nullptr, DD, 1.f, 0, 0);
        gemm_kernel<<<gProj, 256>>>(h, DD, 0, wk_l, DD, 0, 0, k, DD, 0,
                                    nullptr, nullptr, DD, 1.f, 0, 0);
        gemm_kernel<<<gProj, 256>>>(h, DD, 0, wv_l, DD, 0, 0, v, DD, 0,
                                    nullptr, nullptr, DD, 1.f, 0, 0);

        // Scores: S[b,h] = (Q_h @ K_h^T) * scale   (causal blocks skipped)
        for (int b = 0; b < BB; b++) {
            gemm_kernel<<<gScr, 256>>>(
                q + (size_t)b*TT*DD, DD, HD,
                k + (size_t)b*TT*DD, DD, HD, 1 /*transB*/,
                s + (size_t)b*HH*TT*TT, TT, (long long)TT*TT,
                nullptr, nullptr, HD, scale, 0, 1 /*causal*/);
        }

        // Causal softmax (also zeroes masked tail)
        softmax_kernel<<<BB*HH*TT, 128>>>(s);

        // O = P @ V
        for (int b = 0; b < BB; b++) {
            gemm_kernel<<<gPV, 256>>>(
                s + (size_t)b*HH*TT*TT, TT, (long long)TT*TT,
                v + (size_t)b*TT*DD, DD, HD, 0,
                o + (size_t)b*TT*DD, DD, HD,
                nullptr, nullptr, TT, 1.f, 0, 0);
        }

        // x = x + O @ wo + bo
        gemm_kernel<<<gProj, 256>>>(o, DD, 0, wo_l, DD, 0, 0, x, DD, 0,
                                    bo + l*DD, x, DD, 1.f, 0, 0);

        // LN2 + MLP
        ln_kernel<<<ROWS, 256>>>(x, h, ln2_g + l*DD, ln2_b + l*DD);
        gemm_kernel<<<gMlp1, 256>>>(h, DD, 0, w1_l, D4, 0, 0, mbuf, D4, 0,
                                    b1 + (size_t)l*D4, nullptr, DD, 1.f, 1 /*relu*/, 0);
        gemm_kernel<<<gProj, 256>>>(mbuf, D4, 0, w2_l, DD, 0, 0, x, DD, 0,
                                    b2 + l*DD, x, D4, 1.f, 0, 0);
    }

    // Final LN + LM head into d_out
    ln_kernel<<<ROWS, 256>>>(x, h, lnf_g, lnf_b);
    dim3 gLM(VV/GBN, ROWS/GBM);                // (500, 32)
    gemm_kernel<<<gLM, 256>>>(h, DD, 0, w_lm, VV, 0, 0,
                              (float*)d_out, VV, 0,
                              b_lm, nullptr, DD, 1.f, 0, 0);
}

// round 3
// speedup vs baseline: 1.5239x; 1.5239x over previous
#include <cuda_runtime.h>
#include <cuda_bf16.h>
#include <math.h>
#include <stdint.h>

// Problem constants (MiniGPT: B=4, T=1024, D=768, H=12, L=4, V=32000, HD=64)
#define BB 4
#define TT 1024
#define DD 768
#define HH 12
#define LL 4
#define VV 32000
#define HD 64
#define D4 (4*DD)

// GEMM tile sizes
#define BB_M 128
#define BB_N 64
#define BB_K 32

// ---------------------------------------------------------------------------
// Scratch (device globals — no allocations allowed)
// ---------------------------------------------------------------------------
__device__ float g_x[BB*TT*DD];
__device__ float g_h[BB*TT*DD];
__device__ float g_q[BB*TT*DD];
__device__ float g_k[BB*TT*DD];
__device__ float g_v[BB*TT*DD];
__device__ float g_o[BB*TT*DD];
__device__ float g_s[(size_t)BB*HH*TT*TT];   // scores/probs (201 MB)
__device__ float g_m[(size_t)BB*TT*D4];      // MLP hidden

// ---------------------------------------------------------------------------
// Embedding
// ---------------------------------------------------------------------------
__global__ void embed_kernel(const int* __restrict__ idx,
                             const float* __restrict__ tok,
                             const float* __restrict__ pos,
                             float* __restrict__ x) {
    int i = blockIdx.x * blockDim.x + threadIdx.x;
    if (i >= BB*TT*DD) return;
    int d  = i % DD;
    int bt = i / DD;
    int t  = bt % TT;
    x[i] = tok[(size_t)idx[bt]*DD + d] + pos[(size_t)t*DD + d];
}

// ---------------------------------------------------------------------------
// LayerNorm (D=768), one 256-thread block per row
// ---------------------------------------------------------------------------
__global__ void ln_kernel(const float* __restrict__ in, float* __restrict__ out,
                          const float* __restrict__ gw, const float* __restrict__ bw) {
    int row = blockIdx.x;
    const float* x = in  + (size_t)row*DD;
    float*       y = out + (size_t)row*DD;
    int tid = threadIdx.x;

    float s = 0.f, s2 = 0.f;
    for (int i = tid; i < DD; i += 256) { float v = x[i]; s += v; s2 += v*v; }
    #pragma unroll
    for (int o = 16; o; o >>= 1) {
        s  += __shfl_xor_sync(0xffffffffu, s,  o);
        s2 += __shfl_xor_sync(0xffffffffu, s2, o);
    }
    __shared__ float r1[8], r2[8];
    __shared__ float smean, sinv;
    int w = tid >> 5;
    if ((tid & 31) == 0) { r1[w] = s; r2[w] = s2; }
    __syncthreads();
    if (tid == 0) {
        float a = 0.f, b2 = 0.f;
        #pragma unroll
        for (int i = 0; i < 8; i++) { a += r1[i]; b2 += r2[i]; }
        float mean = a / DD;
        float var  = b2 / DD - mean*mean;
        smean = mean;
        sinv  = rsqrtf(var + 1e-5f);
    }
    __syncthreads();
    float mean = smean, inv = sinv;
    for (int i = tid; i < DD; i += 256)
        y[i] = (x[i] - mean) * inv * gw[i] + bw[i];
}

// ---------------------------------------------------------------------------
// Tensor-core GEMM with split-bf16 (3-term) for fp32-equivalent accuracy.
// C = act(alpha * A@B + bias [+ resid])
// Block tile 128x64, BK=32 fp32; 8 warps (4x2); warp tile 32x32; mma m16n8k16.
// ---------------------------------------------------------------------------
__device__ __forceinline__ void ldsm4(uint32_t &r0, uint32_t &r1, uint32_t &r2, uint32_t &r3, uint32_t a) {
    asm volatile("ldmatrix.sync.aligned.m8n8.x4.shared.b16 {%0,%1,%2,%3}, [%4];\n"
                 : "=r"(r0), "=r"(r1), "=r"(r2), "=r"(r3) : "r"(a));
}
__device__ __forceinline__ void mma16816(float* d, const uint32_t* a, uint32_t b0, uint32_t b1) {
    asm volatile("mma.sync.aligned.m16n8k16.row.col.f32.bf16.bf16.f32 "
                 "{%0,%1,%2,%3},{%4,%5,%6,%7},{%8,%9},{%0,%1,%2,%3};\n"
                 : "+f"(d[0]), "+f"(d[1]), "+f"(d[2]), "+f"(d[3])
                 : "r"(a[0]), "r"(a[1]), "r"(a[2]), "r"(a[3]), "r"(b0), "r"(b1));
}
// byte offset of b32 word kw (0..15) in a 64B row, XOR-swizzled for ldmatrix
__device__ __forceinline__ uint32_t swz(int row, int kw) {
    int c = (kw >> 2) ^ ((row >> 1) & 3);
    return (uint32_t)(row * 64 + ((c << 2) | (kw & 3)) * 4);
}
__device__ __forceinline__ void split2(float x, float y, uint32_t &hi, uint32_t &lo) {
    __nv_bfloat16 xh = __float2bfloat16_rn(x), yh = __float2bfloat16_rn(y);
    __nv_bfloat16 xl = __float2bfloat16_rn(x - __bfloat162float(xh));
    __nv_bfloat16 yl = __float2bfloat16_rn(y - __bfloat162float(yh));
    hi = (uint32_t)__bfloat16_as_ushort(xh) | ((uint32_t)__bfloat16_as_ushort(yh) << 16);
    lo = (uint32_t)__bfloat16_as_ushort(xl) | ((uint32_t)__bfloat16_as_ushort(yl) << 16);
}
__device__ __forceinline__ void split1(float x, uint16_t &h, uint16_t &l) {
    __nv_bfloat16 xh = __float2bfloat16_rn(x);
    h = __bfloat16_as_ushort(xh);
    l = __bfloat16_as_ushort(__float2bfloat16_rn(x - __bfloat162float(xh)));
}

__global__ __launch_bounds__(256, 2)
void gemm_tc(const float* __restrict__ A, int lda, long long sA,
             const float* __restrict__ Bp, int ldb, long long sB, int transB,
             float* __restrict__ C, int ldc, long long sC,
             const float* __restrict__ bias,
             const float* __restrict__ resid,
             int K, float alpha, int relu, int causal) {
    int bz = blockIdx.z;
    A  += sA * bz;
    Bp += sB * bz;
    C  += sC * bz;
    if (resid) resid += sC * bz;

    int bm = blockIdx.y * BB_M;
    int bn = blockIdx.x * BB_N;
    if (causal && bn >= bm + BB_M) return;

    __shared__ __align__(16) uint8_t smbuf[24576];
    uint8_t* As_hi = smbuf;             // 128*64B = 8192
    uint8_t* As_lo = smbuf + 8192;
    uint8_t* Bs_hi = smbuf + 16384;     // 64*64B = 4096
    uint8_t* Bs_lo = smbuf + 20480;
    uint32_t sa_hi = (uint32_t)__cvta_generic_to_shared(As_hi);
    uint32_t sa_lo = (uint32_t)__cvta_generic_to_shared(As_lo);
    uint32_t sb_hi = (uint32_t)__cvta_generic_to_shared(Bs_hi);
    uint32_t sb_lo = (uint32_t)__cvta_generic_to_shared(Bs_lo);

    int tid = threadIdx.x;
    int lane = tid & 31, warp = tid >> 5;
    int wm = warp & 3, wn = warp >> 2;

    float acc[2][4][4];
    #pragma unroll
    for (int i = 0; i < 2; i++)
        #pragma unroll
        for (int j = 0; j < 4; j++)
            #pragma unroll
            for (int e = 0; e < 4; e++) acc[i][j][e] = 0.f;

    int nk = K / BB_K;
    float4 ag[4], bg[2];

    // ---- global tile load (registers) ----
    auto load_tile = [&](int kb) {
        int k0 = kb * BB_K;
        #pragma unroll
        for (int j = 0; j < 4; j++) {
            int lin = tid + j * 256;
            int ar = lin >> 3, ac = (lin & 7) * 4;
            ag[j] = *(const float4*)(A + (long long)(bm + ar) * lda + k0 + ac);
        }
        if (transB) {
            #pragma unroll
            for (int j = 0; j < 2; j++) {
                int lin = tid + j * 256;
                int br = lin >> 3, bc = (lin & 7) * 4;
                bg[j] = *(const float4*)(Bp + (long long)(bn + br) * ldb + k0 + bc);
            }
        } else {
            #pragma unroll
            for (int j = 0; j < 2; j++) {
                int lin = tid + j * 256;
                int kr = lin >> 4, nq = (lin & 15) * 4;
                bg[j] = *(const float4*)(Bp + (long long)(k0 + kr) * ldb + bn + nq);
            }
        }
    };

    // ---- smem store with fp32 -> (hi,lo) bf16 conversion ----
    auto store_tile = [&]() {
        #pragma unroll
        for (int j = 0; j < 4; j++) {
            int lin = tid + j * 256;
            int ar = lin >> 3, ac = (lin & 7) * 4;
            int kw = ac >> 1;
            uint32_t h0, l0, h1, l1;
            split2(ag[j].x, ag[j].y, h0, l0);
            split2(ag[j].z, ag[j].w, h1, l1);
            uint32_t o0 = swz(ar, kw), o1 = swz(ar, kw + 1);
            *(uint32_t*)(As_hi + o0) = h0;
            *(uint32_t*)(As_hi + o1) = h1;
            *(uint32_t*)(As_lo + o0) = l0;
            *(uint32_t*)(As_lo + o1) = l1;
        }
        if (transB) {
            #pragma unroll
            for (int j = 0; j < 2; j++) {
                int lin = tid + j * 256;
                int br = lin >> 3, bc = (lin & 7) * 4;
                int kw = bc >> 1;
                uint32_t h0, l0, h1, l1;
                split2(bg[j].x, bg[j].y, h0, l0);
                split2(bg[j].z, bg[j].w, h1, l1);
                uint32_t o0 = swz(br, kw), o1 = swz(br, kw + 1);
                *(uint32_t*)(Bs_hi + o0) = h0;
                *(uint32_t*)(Bs_hi + o1) = h1;
                *(uint32_t*)(Bs_lo + o0) = l0;
                *(uint32_t*)(Bs_lo + o1) = l1;
            }
        } else {
            #pragma unroll
            for (int j = 0; j < 2; j++) {
                int lin = tid + j * 256;
                int kr = lin >> 4, nq = (lin & 15) * 4;
                float v[4] = {bg[j].x, bg[j].y, bg[j].z, bg[j].w};
                #pragma unroll
                for (int e = 0; e < 4; e++) {
                    uint16_t h, l;
                    split1(v[e], h, l);
                    uint32_t off = swz(nq + e, kr >> 1) + ((kr & 1) << 1);
                    *(uint16_t*)(Bs_hi + off) = h;
                    *(uint16_t*)(Bs_lo + off) = l;
                }
            }
        }
    };

    load_tile(0);

    for (int kb = 0; kb < nk; kb++) {
        store_tile();
        __syncthreads();
        if (kb + 1 < nk) load_tile(kb + 1);

        #pragma unroll
        for (int ks = 0; ks < 2; ks++) {
            uint32_t ah[2][4], al[2][4], bh[2][4], bl[2][4];
            int chunk = ks * 2 + (lane >> 4);
            int rowA0 = wm * 32 + (lane & 15);
            #pragma unroll
            for (int mm = 0; mm < 2; mm++) {
                int r = rowA0 + mm * 16;
                uint32_t off = (uint32_t)(r * 64 + ((chunk ^ ((r >> 1) & 3)) << 4));
                ldsm4(ah[mm][0], ah[mm][1], ah[mm][2], ah[mm][3], sa_hi + off);
                ldsm4(al[mm][0], al[mm][1], al[mm][2], al[mm][3], sa_lo + off);
            }
            int rowB0 = wn * 32 + (lane & 15);
            #pragma unroll
            for (int nb = 0; nb < 2; nb++) {
                int r = rowB0 + nb * 16;
                uint32_t off = (uint32_t)(r * 64 + ((chunk ^ ((r >> 1) & 3)) << 4));
                ldsm4(bh[nb][0], bh[nb][1], bh[nb][2], bh[nb][3], sb_hi + off);
                ldsm4(bl[nb][0], bl[nb][1], bl[nb][2], bl[nb][3], sb_lo + off);
            }
            #pragma unroll
            for (int mm = 0; mm < 2; mm++) {
                #pragma unroll
                for (int nf = 0; nf < 4; nf++) {
                    uint32_t b0h = bh[nf >> 1][nf & 1], b1h = bh[nf >> 1][(nf & 1) + 2];
                    uint32_t b0l = bl[nf >> 1][nf & 1], b1l = bl[nf >> 1][(nf & 1) + 2];
                    mma16816(acc[mm][nf], ah[mm], b0h, b1h);
                    mma16816(acc[mm][nf], ah[mm], b0l, b1l);
                    mma16816(acc[mm][nf], al[mm], b0h, b1h);
                }
            }
        }
        __syncthreads();
    }

    // ---- epilogue ----
    int ml = lane >> 2, nl = (lane & 3) * 2;
    #pragma unroll
    for (int mm = 0; mm < 2; mm++) {
        #pragma unroll
        for (int nf = 0; nf < 4; nf++) {
            int col = bn + wn * 32 + nf * 8 + nl;
            float bx = 0.f, by = 0.f;
            if (bias) { float2 bb = *(const float2*)(bias + col); bx = bb.x; by = bb.y; }
            int r0 = bm + wm * 32 + mm * 16 + ml;
            #pragma unroll
            for (int h = 0; h < 2; h++) {
                int r = r0 + h * 8;
                long long off = (long long)r * ldc + col;
                float2 v;
                v.x = acc[mm][nf][h * 2 + 0] * alpha + bx;
                v.y = acc[mm][nf][h * 2 + 1] * alpha + by;
                if (resid) {
                    float2 rr = *(const float2*)(resid + off);
                    v.x += rr.x; v.y += rr.y;
                }
                if (relu) { v.x = fmaxf(v.x, 0.f); v.y = fmaxf(v.y, 0.f); }
                *(float2*)(C + off) = v;
            }
        }
    }
}

// ---------------------------------------------------------------------------
// Causal softmax
// ---------------------------------------------------------------------------
__global__ void softmax_kernel(float* __restrict__ s) {
    long long row = blockIdx.x;
    int q = (int)(row % TT);
    float* p = s + row * (long long)TT;
    int n = q + 1;
    int tid = threadIdx.x;

    float m = -1e30f;
    for (int i = tid; i < n; i += 128) m = fmaxf(m, p[i]);
    #pragma unroll
    for (int o = 16; o; o >>= 1) m = fmaxf(m, __shfl_xor_sync(0xffffffffu, m, o));

    __shared__ float red[4];
    __shared__ float bm, bsum;
    if ((tid & 31) == 0) red[tid >> 5] = m;
    __syncthreads();
    if (tid == 0) {
        float v = red[0];
        #pragma unroll
        for (int i = 1; i < 4; i++) v = fmaxf(v, red[i]);
        bm = v;
    }
    __syncthreads();
    m = bm;

    float sum = 0.f;
    for (int i = tid; i < n; i += 128) {
        float e = expf(p[i] - m);
        p[i] = e;
        sum += e;
    }
    #pragma unroll
    for (int o = 16; o; o >>= 1) sum += __shfl_xor_sync(0xffffffffu, sum, o);
    __syncthreads();
    if ((tid & 31) == 0) red[tid >> 5] = sum;
    __syncthreads();
    if (tid == 0) {
        float v = 0.f;
        #pragma unroll
        for (int i = 0; i < 4; i++) v += red[i];
        bsum = v;
    }
    __syncthreads();
    float inv = 1.f / bsum;
    for (int i = tid; i < n; i += 128) p[i] *= inv;
    for (int i = n + tid; i < TT; i += 128) p[i] = 0.f;
}

// ---------------------------------------------------------------------------
// Host orchestration
// ---------------------------------------------------------------------------
extern "C" void kernel_launch(void* const* d_in, const int* in_sizes, int n_in,
                              void* d_out, int out_size) {
    const int*   idx    = (const int*)  d_in[0];
    const float* tok    = (const float*)d_in[1];
    const float* pos    = (const float*)d_in[2];
    const float* wq     = (const float*)d_in[3];
    const float* wk     = (const float*)d_in[4];
    const float* wv     = (const float*)d_in[5];
    const float* wo     = (const float*)d_in[6];
    const float* bo     = (const float*)d_in[7];
    const float* ln1_g  = (const float*)d_in[8];
    const float* ln1_b  = (const float*)d_in[9];
    const float* ln2_g  = (const float*)d_in[10];
    const float* ln2_b  = (const float*)d_in[11];
    const float* w1     = (const float*)d_in[12];
    const float* b1     = (const float*)d_in[13];
    const float* w2     = (const float*)d_in[14];
    const float* b2     = (const float*)d_in[15];
    const float* lnf_g  = (const float*)d_in[16];
    const float* lnf_b  = (const float*)d_in[17];
    const float* w_lm   = (const float*)d_in[18];
    const float* b_lm   = (const float*)d_in[19];

    float *x, *h, *q, *k, *v, *o, *s, *mbuf;
    cudaGetSymbolAddress((void**)&x,    g_x);
    cudaGetSymbolAddress((void**)&h,    g_h);
    cudaGetSymbolAddress((void**)&q,    g_q);
    cudaGetSymbolAddress((void**)&k,    g_k);
    cudaGetSymbolAddress((void**)&v,    g_v);
    cudaGetSymbolAddress((void**)&o,    g_o);
    cudaGetSymbolAddress((void**)&s,    g_s);
    cudaGetSymbolAddress((void**)&mbuf, g_m);

    const int ROWS = BB * TT;
    const float scale = 0.125f;

    embed_kernel<<<(BB*TT*DD + 255)/256, 256>>>(idx, tok, pos, x);

    dim3 gProj(DD/BB_N,  ROWS/BB_M);
    dim3 gMlp1(D4/BB_N,  ROWS/BB_M);
    dim3 gScr (TT/BB_N,  TT/BB_M, HH);
    dim3 gPV  (HD/BB_N,  TT/BB_M, HH);

    for (int l = 0; l < LL; l++) {
        const float* wq_l = wq + (size_t)l*DD*DD;
        const float* wk_l = wk + (size_t)l*DD*DD;
        const float* wv_l = wv + (size_t)l*DD*DD;
        const float* wo_l = wo + (size_t)l*DD*DD;
        const float* w1_l = w1 + (size_t)l*DD*D4;
        const float* w2_l = w2 + (size_t)l*D4*DD;

        ln_kernel<<<ROWS, 256>>>(x, h, ln1_g + l*DD, ln1_b + l*DD);

        gemm_tc<<<gProj, 256>>>(h, DD, 0, wq_l, DD, 0, 0, q, DD, 0,
                                nullptr, nullptr, DD, 1.f, 0, 0);
        gemm_tc<<<gProj, 256>>>(h, DD, 0, wk_l, DD, 0, 0, k, DD, 0,
                                nullptr, nullptr, DD, 1.f, 0, 0);
        gemm_tc<<<gProj, 256>>>(h, DD, 0, wv_l, DD, 0, 0, v, DD, 0,
                                nullptr, nullptr, DD, 1.f, 0, 0);

        for (int b = 0; b < BB; b++) {
            gemm_tc<<<gScr, 256>>>(
                q + (size_t)b*TT*DD, DD, HD,
                k + (size_t)b*TT*DD, DD, HD, 1,
                s + (size_t)b*HH*TT*TT, TT, (long long)TT*TT,
                nullptr, nullptr, HD, scale, 0, 1);
        }

        softmax_kernel<<<BB*HH*TT, 128>>>(s);

        for (int b = 0; b < BB; b++) {
            gemm_tc<<<gPV, 256>>>(
                s + (size_t)b*HH*TT*TT, TT, (long long)TT*TT,
                v + (size_t)b*TT*DD, DD, HD, 0,
                o + (size_t)b*TT*DD, DD, HD,
                nullptr, nullptr, TT, 1.f, 0, 0);
        }

        gemm_tc<<<gProj, 256>>>(o, DD, 0, wo_l, DD, 0, 0, x, DD, 0,
                                bo + l*DD, x, DD, 1.f, 0, 0);

        ln_kernel<<<ROWS, 256>>>(x, h, ln2_g + l*DD, ln2_b + l*DD);
        gemm_tc<<<gMlp1, 256>>>(h, DD, 0, w1_l, D4, 0, 0, mbuf, D4, 0,
                                b1 + (size_t)l*D4, nullptr, DD, 1.f, 1, 0);
        gemm_tc<<<gProj, 256>>>(mbuf, D4, 0, w2_l, DD, 0, 0, x, DD, 0,
                                b2 + l*DD, x, D4, 1.f, 0, 0);
    }

    ln_kernel<<<ROWS, 256>>>(x, h, lnf_g, lnf_b);
    dim3 gLM(VV/BB_N, ROWS/BB_M);
    gemm_tc<<<gLM, 256>>>(h, DD, 0, w_lm, VV, 0, 0,
                          (float*)d_out, VV, 0,
                          b_lm, nullptr, DD, 1.f, 0, 0);
}

// round 4
// speedup vs baseline: 2.8313x; 1.8579x over previous
#include <cuda_runtime.h>
#include <cuda_bf16.h>
#include <math.h>
#include <stdint.h>

// Problem constants (MiniGPT: B=4, T=1024, D=768, H=12, L=4, V=32000, HD=64)
#define BB 4
#define TT 1024
#define DD 768
#define HH 12
#define LL 4
#define VV 32000
#define HD 64
#define D4 (4*DD)

// ---------------------------------------------------------------------------
// Scratch (device globals). All bf16 "planes" are (hi, lo) split pairs.
// ---------------------------------------------------------------------------
__device__ float g_x[BB*TT*DD];
__device__ float g_s[(size_t)BB*HH*TT*TT];

#define PLANE(name, n) \
  __device__ __align__(256) __nv_bfloat16 name##_hi[n]; \
  __device__ __align__(256) __nv_bfloat16 name##_lo[n];

PLANE(g_h,  BB*TT*DD)
PLANE(g_q,  BB*TT*DD)
PLANE(g_k,  BB*TT*DD)
PLANE(g_vT, BB*TT*DD)                 // [b][d][t] transposed V
PLANE(g_o,  BB*TT*DD)
PLANE(g_p,  (size_t)BB*HH*TT*TT)      // probs
PLANE(g_m,  (size_t)BB*TT*D4)         // MLP hidden
// transposed weights [N,K]
PLANE(g_wqT, LL*DD*DD)
PLANE(g_wkT, LL*DD*DD)
PLANE(g_wvT, LL*DD*DD)
PLANE(g_woT, LL*DD*DD)
PLANE(g_w1T, (size_t)LL*D4*DD)
PLANE(g_w2T, (size_t)LL*DD*D4)
PLANE(g_wlmT, (size_t)VV*DD)

// ---------------------------------------------------------------------------
// Helpers
// ---------------------------------------------------------------------------
__device__ __forceinline__ void split1(float x, __nv_bfloat16 &h, __nv_bfloat16 &l) {
    h = __float2bfloat16_rn(x);
    l = __float2bfloat16_rn(x - __bfloat162float(h));
}
__device__ __forceinline__ void split2pack(float x, float y, uint32_t &hi, uint32_t &lo) {
    __nv_bfloat16 xh, xl, yh, yl;
    split1(x, xh, xl); split1(y, yh, yl);
    hi = (uint32_t)__bfloat16_as_ushort(xh) | ((uint32_t)__bfloat16_as_ushort(yh) << 16);
    lo = (uint32_t)__bfloat16_as_ushort(xl) | ((uint32_t)__bfloat16_as_ushort(yl) << 16);
}
__device__ __forceinline__ void ldsm4(uint32_t &r0, uint32_t &r1, uint32_t &r2, uint32_t &r3, uint32_t a) {
    asm volatile("ldmatrix.sync.aligned.m8n8.x4.shared.b16 {%0,%1,%2,%3}, [%4];\n"
                 : "=r"(r0), "=r"(r1), "=r"(r2), "=r"(r3) : "r"(a));
}
__device__ __forceinline__ void mma16816(float* d, const uint32_t* a, uint32_t b0, uint32_t b1) {
    asm volatile("mma.sync.aligned.m16n8k16.row.col.f32.bf16.bf16.f32 "
                 "{%0,%1,%2,%3},{%4,%5,%6,%7},{%8,%9},{%0,%1,%2,%3};\n"
                 : "+f"(d[0]), "+f"(d[1]), "+f"(d[2]), "+f"(d[3])
                 : "r"(a[0]), "r"(a[1]), "r"(a[2]), "r"(a[3]), "r"(b0), "r"(b1));
}
__device__ __forceinline__ void cpa16(uint32_t dst, const void* src) {
    asm volatile("cp.async.cg.shared.global [%0], [%1], 16;\n" :: "r"(dst), "l"(src));
}
__device__ __forceinline__ void cp_commit() { asm volatile("cp.async.commit_group;\n"); }
__device__ __forceinline__ void cp_wait1() { asm volatile("cp.async.wait_group 1;\n"); }
__device__ __forceinline__ void cp_wait0() { asm volatile("cp.async.wait_group 0;\n"); }
// byte offset of 16B chunk c (0..3) in a 64B row, XOR swizzle for ldmatrix
__device__ __forceinline__ uint32_t swzc(int row, int c) {
    return (uint32_t)(row * 64 + ((c ^ ((row >> 1) & 3)) << 4));
}

// ---------------------------------------------------------------------------
// Weight prep: transpose [K,N] fp32 -> [N,K] bf16 hi/lo planes. z = layer.
// ---------------------------------------------------------------------------
__global__ void transpose_split(const float* __restrict__ in,
                                __nv_bfloat16* __restrict__ oh,
                                __nv_bfloat16* __restrict__ ol,
                                int K, int N) {
    in += (size_t)blockIdx.z * K * N;
    oh += (size_t)blockIdx.z * N * K;
    ol += (size_t)blockIdx.z * N * K;
    __shared__ float tile[32][33];
    int n0 = blockIdx.x * 32, k0 = blockIdx.y * 32;
    int tx = threadIdx.x, ty = threadIdx.y;
    #pragma unroll
    for (int i = 0; i < 4; i++)
        tile[ty + i*8][tx] = in[(size_t)(k0 + ty + i*8) * N + n0 + tx];
    __syncthreads();
    #pragma unroll
    for (int i = 0; i < 4; i++) {
        float v = tile[tx][ty + i*8];
        __nv_bfloat16 h, l;
        split1(v, h, l);
        size_t off = (size_t)(n0 + ty + i*8) * K + k0 + tx;
        oh[off] = h;
        ol[off] = l;
    }
}

// ---------------------------------------------------------------------------
// Embedding
// ---------------------------------------------------------------------------
__global__ void embed_kernel(const int* __restrict__ idx,
                             const float* __restrict__ tok,
                             const float* __restrict__ pos,
                             float* __restrict__ x) {
    int i = blockIdx.x * blockDim.x + threadIdx.x;
    if (i >= BB*TT*DD) return;
    int d  = i % DD;
    int bt = i / DD;
    int t  = bt % TT;
    x[i] = tok[(size_t)idx[bt]*DD + d] + pos[(size_t)t*DD + d];
}

// ---------------------------------------------------------------------------
// LayerNorm fp32 -> bf16 hi/lo planes
// ---------------------------------------------------------------------------
__global__ void ln_planes(const float* __restrict__ in,
                          __nv_bfloat16* __restrict__ oh,
                          __nv_bfloat16* __restrict__ ol,
                          const float* __restrict__ gw, const float* __restrict__ bw) {
    int row = blockIdx.x;
    const float* x = in + (size_t)row*DD;
    int tid = threadIdx.x;

    float s = 0.f, s2 = 0.f;
    for (int i = tid; i < DD; i += 256) { float v = x[i]; s += v; s2 += v*v; }
    #pragma unroll
    for (int o = 16; o; o >>= 1) {
        s  += __shfl_xor_sync(0xffffffffu, s,  o);
        s2 += __shfl_xor_sync(0xffffffffu, s2, o);
    }
    __shared__ float r1[8], r2[8];
    __shared__ float smean, sinv;
    int w = tid >> 5;
    if ((tid & 31) == 0) { r1[w] = s; r2[w] = s2; }
    __syncthreads();
    if (tid == 0) {
        float a = 0.f, b2 = 0.f;
        #pragma unroll
        for (int i = 0; i < 8; i++) { a += r1[i]; b2 += r2[i]; }
        float mean = a / DD;
        float var  = b2 / DD - mean*mean;
        smean = mean;
        sinv  = rsqrtf(var + 1e-5f);
    }
    __syncthreads();
    float mean = smean, inv = sinv;
    for (int i = tid; i < DD; i += 256) {
        float y = (x[i] - mean) * inv * gw[i] + bw[i];
        __nv_bfloat16 h, l;
        split1(y, h, l);
        size_t off = (size_t)row*DD + i;
        oh[off] = h;
        ol[off] = l;
    }
}

// ---------------------------------------------------------------------------
// Causal softmax: fp32 scores -> bf16 hi/lo prob planes (masked tail zeroed)
// ---------------------------------------------------------------------------
__global__ void softmax_planes(const float* __restrict__ s,
                               __nv_bfloat16* __restrict__ ph,
                               __nv_bfloat16* __restrict__ pl) {
    long long row = blockIdx.x;
    int q = (int)(row % TT);
    const float* p = s + row * (long long)TT;
    __nv_bfloat16* oh = ph + row * (long long)TT;
    __nv_bfloat16* ol = pl + row * (long long)TT;
    int n = q + 1;
    int tid = threadIdx.x;

    float m = -1e30f;
    for (int i = tid; i < n; i += 128) m = fmaxf(m, p[i]);
    #pragma unroll
    for (int o = 16; o; o >>= 1) m = fmaxf(m, __shfl_xor_sync(0xffffffffu, m, o));

    __shared__ float red[4];
    __shared__ float bm, bsum;
    if ((tid & 31) == 0) red[tid >> 5] = m;
    __syncthreads();
    if (tid == 0) {
        float v = red[0];
        #pragma unroll
        for (int i = 1; i < 4; i++) v = fmaxf(v, red[i]);
        bm = v;
    }
    __syncthreads();
    m = bm;

    float sum = 0.f;
    for (int i = tid; i < n; i += 128) sum += expf(p[i] - m);
    #pragma unroll
    for (int o = 16; o; o >>= 1) sum += __shfl_xor_sync(0xffffffffu, sum, o);
    if ((tid & 31) == 0) red[tid >> 5] = sum;
    __syncthreads();
    if (tid == 0) {
        float v = 0.f;
        #pragma unroll
        for (int i = 0; i < 4; i++) v += red[i];
        bsum = v;
    }
    __syncthreads();
    float inv = 1.f / bsum;
    for (int i = tid; i < n; i += 128) {
        float e = expf(p[i] - m) * inv;
        __nv_bfloat16 h, l;
        split1(e, h, l);
        oh[i] = h;
        ol[i] = l;
    }
    __nv_bfloat16 z = __float2bfloat16_rn(0.f);
    for (int i = n + tid; i < TT; i += 128) { oh[i] = z; ol[i] = z; }
}

// ---------------------------------------------------------------------------
// bf16 split GEMM:  C = act(alpha * A@B^T + bias [+resid])
//   A: [M,K] bf16 hi/lo planes (lda elements), B: [N,K] bf16 hi/lo planes.
//   Block tile 128x64xK32; 8 warps; cp.async double-buffered smem.
//   z decomposition: z1 = z % zmod, z2 = z / zmod (zmod=0 -> z1=z, z2=0).
//   mode 0: fp32 C [ldc, sC/sC2] (+resid/relu/causal)
//   mode 1: bf16 hi/lo planes Ch/Cl [ldcp, sP/sP2] (+bias/relu)
//   mode 2: bf16 hi/lo planes transposed (vT: [b][n][t], r = b*TT+t)
// ---------------------------------------------------------------------------
__global__ __launch_bounds__(256, 3)
void gemm_bf16(const __nv_bfloat16* __restrict__ Ah, const __nv_bfloat16* __restrict__ Al,
               int lda, long long sA, long long sA2,
               const __nv_bfloat16* __restrict__ Bh, const __nv_bfloat16* __restrict__ Bl,
               int ldb, long long sB, long long sB2,
               int K, float alpha, int zmod, int mode,
               float* __restrict__ C, int ldc, long long sC, long long sC2,
               __nv_bfloat16* __restrict__ Ch, __nv_bfloat16* __restrict__ Cl,
               int ldcp, long long sP, long long sP2,
               const float* __restrict__ bias, const float* __restrict__ resid,
               int relu, int causal) {
    int z = blockIdx.z, z1 = z, z2 = 0;
    if (zmod) { z2 = z / zmod; z1 = z % zmod; }
    Ah += sA*z1 + sA2*z2;  Al += sA*z1 + sA2*z2;
    Bh += sB*z1 + sB2*z2;  Bl += sB*z1 + sB2*z2;
    if (C)  C  += sC*z1 + sC2*z2;
    if (resid) resid += sC*z1 + sC2*z2;
    if (Ch) { Ch += sP*z1 + sP2*z2; Cl += sP*z1 + sP2*z2; }

    int bm = blockIdx.y * 128;
    int bn = blockIdx.x * 64;
    if (causal && bn >= bm + 128) return;

    // double-buffered: per buffer A_hi 8K | A_lo 8K | B_hi 4K | B_lo 4K
    __shared__ __align__(16) uint8_t smbuf[2 * 24576];
    uint32_t smbase = (uint32_t)__cvta_generic_to_shared(smbuf);

    int tid = threadIdx.x;
    int lane = tid & 31, warp = tid >> 5;
    int wm = warp & 3, wn = warp >> 2;

    int nk = K / 32;

    auto issue = [&](int kb) {
        int k0 = kb * 32;
        uint32_t base = smbase + (kb & 1) * 24576;
        #pragma unroll
        for (int j = 0; j < 4; j++) {
            int lin = tid + j * 256;          // 0..1023
            int pl = lin >> 9, rc = lin & 511, r = rc >> 2, c = rc & 3;
            const __nv_bfloat16* src = (pl ? Al : Ah) + (long long)(bm + r) * lda + k0 + c * 8;
            cpa16(base + pl * 8192 + swzc(r, c), src);
        }
        #pragma unroll
        for (int j = 0; j < 2; j++) {
            int lin = tid + j * 256;          // 0..511
            int pl = lin >> 8, rc = lin & 255, r = rc >> 2, c = rc & 3;
            const __nv_bfloat16* src = (pl ? Bl : Bh) + (long long)(bn + r) * ldb + k0 + c * 8;
            cpa16(base + 16384 + pl * 4096 + swzc(r, c), src);
        }
        cp_commit();
    };

    float acc[2][4][4];
    #pragma unroll
    for (int i = 0; i < 2; i++)
        #pragma unroll
        for (int j = 0; j < 4; j++)
            #pragma unroll
            for (int e = 0; e < 4; e++) acc[i][j][e] = 0.f;

    issue(0);
    if (nk > 1) issue(1);

    for (int kb = 0; kb < nk; kb++) {
        if (kb + 1 < nk) cp_wait1(); else cp_wait0();
        __syncthreads();
        uint32_t base = smbase + (kb & 1) * 24576;

        #pragma unroll
        for (int ks = 0; ks < 2; ks++) {
            uint32_t ah[2][4], al[2][4], bh[2][4], bl[2][4];
            int chunk = ks * 2 + (lane >> 4);
            int rowA0 = wm * 32 + (lane & 15);
            #pragma unroll
            for (int mm = 0; mm < 2; mm++) {
                int r = rowA0 + mm * 16;
                uint32_t off = (uint32_t)(r * 64 + ((chunk ^ ((r >> 1) & 3)) << 4));
                ldsm4(ah[mm][0], ah[mm][1], ah[mm][2], ah[mm][3], base + off);
                ldsm4(al[mm][0], al[mm][1], al[mm][2], al[mm][3], base + 8192 + off);
            }
            int rowB0 = wn * 32 + (lane & 15);
            #pragma unroll
            for (int nb = 0; nb < 2; nb++) {
                int r = rowB0 + nb * 16;
                uint32_t off = (uint32_t)(r * 64 + ((chunk ^ ((r >> 1) & 3)) << 4));
                ldsm4(bh[nb][0], bh[nb][1], bh[nb][2], bh[nb][3], base + 16384 + off);
                ldsm4(bl[nb][0], bl[nb][1], bl[nb][2], bl[nb][3], base + 20480 + off);
            }
            #pragma unroll
            for (int mm = 0; mm < 2; mm++) {
                #pragma unroll
                for (int nf = 0; nf < 4; nf++) {
                    uint32_t b0h = bh[nf >> 1][nf & 1], b1h = bh[nf >> 1][(nf & 1) + 2];
                    uint32_t b0l = bl[nf >> 1][nf & 1], b1l = bl[nf >> 1][(nf & 1) + 2];
                    mma16816(acc[mm][nf], ah[mm], b0h, b1h);
                    mma16816(acc[mm][nf], ah[mm], b0l, b1l);
                    mma16816(acc[mm][nf], al[mm], b0h, b1h);
                }
            }
        }
        __syncthreads();
        if (kb + 2 < nk) issue(kb + 2);
    }

    // ---- epilogue ----
    int ml = lane >> 2, nl = (lane & 3) * 2;
    #pragma unroll
    for (int mm = 0; mm < 2; mm++) {
        #pragma unroll
        for (int nf = 0; nf < 4; nf++) {
            int col = bn + wn * 32 + nf * 8 + nl;
            float bx = 0.f, by = 0.f;
            if (bias) { float2 bb = *(const float2*)(bias + col); bx = bb.x; by = bb.y; }
            int r0 = bm + wm * 32 + mm * 16 + ml;
            #pragma unroll
            for (int hh = 0; hh < 2; hh++) {
                int r = r0 + hh * 8;
                float vx = acc[mm][nf][hh * 2 + 0] * alpha + bx;
                float vy = acc[mm][nf][hh * 2 + 1] * alpha + by;
                if (mode == 0) {
                    long long off = (long long)r * ldc + col;
                    if (resid) {
                        float2 rr = *(const float2*)(resid + off);
                        vx += rr.x; vy += rr.y;
                    }
                    if (relu) { vx = fmaxf(vx, 0.f); vy = fmaxf(vy, 0.f); }
                    float2 v; v.x = vx; v.y = vy;
                    *(float2*)(C + off) = v;
                } else if (mode == 1) {
                    if (relu) { vx = fmaxf(vx, 0.f); vy = fmaxf(vy, 0.f); }
                    long long off = (long long)r * ldcp + col;
                    uint32_t hi, lo;
                    split2pack(vx, vy, hi, lo);
                    *(uint32_t*)(Ch + off) = hi;
                    *(uint32_t*)(Cl + off) = lo;
                } else { // mode 2: vT[b][col][t], r = b*TT + t
                    int b = r >> 10, t = r & 1023;
                    long long off = ((long long)b * DD + col) * TT + t;
                    __nv_bfloat16 h0, l0, h1, l1;
                    split1(vx, h0, l0);
                    split1(vy, h1, l1);
                    Ch[off] = h0;       Cl[off] = l0;
                    Ch[off + TT] = h1;  Cl[off + TT] = l1;
                }
            }
        }
    }
}

// ---------------------------------------------------------------------------
// Host orchestration
// ---------------------------------------------------------------------------
#define GETSYM(p, sym) cudaGetSymbolAddress((void**)&p, sym)

extern "C" void kernel_launch(void* const* d_in, const int* in_sizes, int n_in,
                              void* d_out, int out_size) {
    const int*   idx    = (const int*)  d_in[0];
    const float* tok    = (const float*)d_in[1];
    const float* pos    = (const float*)d_in[2];
    const float* wq     = (const float*)d_in[3];
    const float* wk     = (const float*)d_in[4];
    const float* wv     = (const float*)d_in[5];
    const float* wo     = (const float*)d_in[6];
    const float* bo     = (const float*)d_in[7];
    const float* ln1_g  = (const float*)d_in[8];
    const float* ln1_b  = (const float*)d_in[9];
    const float* ln2_g  = (const float*)d_in[10];
    const float* ln2_b  = (const float*)d_in[11];
    const float* w1     = (const float*)d_in[12];
    const float* b1     = (const float*)d_in[13];
    const float* w2     = (const float*)d_in[14];
    const float* b2     = (const float*)d_in[15];
    const float* lnf_g  = (const float*)d_in[16];
    const float* lnf_b  = (const float*)d_in[17];
    const float* w_lm   = (const float*)d_in[18];
    const float* b_lm   = (const float*)d_in[19];

    float *x, *s;
    GETSYM(x, g_x); GETSYM(s, g_s);
    __nv_bfloat16 *h_hi,*h_lo,*q_hi,*q_lo,*k_hi,*k_lo,*vT_hi,*vT_lo,*o_hi,*o_lo,
                  *p_hi,*p_lo,*m_hi,*m_lo,
                  *wqT_hi,*wqT_lo,*wkT_hi,*wkT_lo,*wvT_hi,*wvT_lo,*woT_hi,*woT_lo,
                  *w1T_hi,*w1T_lo,*w2T_hi,*w2T_lo,*wlmT_hi,*wlmT_lo;
    GETSYM(h_hi, g_h_hi);   GETSYM(h_lo, g_h_lo);
    GETSYM(q_hi, g_q_hi);   GETSYM(q_lo, g_q_lo);
    GETSYM(k_hi, g_k_hi);   GETSYM(k_lo, g_k_lo);
    GETSYM(vT_hi, g_vT_hi); GETSYM(vT_lo, g_vT_lo);
    GETSYM(o_hi, g_o_hi);   GETSYM(o_lo, g_o_lo);
    GETSYM(p_hi, g_p_hi);   GETSYM(p_lo, g_p_lo);
    GETSYM(m_hi, g_m_hi);   GETSYM(m_lo, g_m_lo);
    GETSYM(wqT_hi, g_wqT_hi); GETSYM(wqT_lo, g_wqT_lo);
    GETSYM(wkT_hi, g_wkT_hi); GETSYM(wkT_lo, g_wkT_lo);
    GETSYM(wvT_hi, g_wvT_hi); GETSYM(wvT_lo, g_wvT_lo);
    GETSYM(woT_hi, g_woT_hi); GETSYM(woT_lo, g_woT_lo);
    GETSYM(w1T_hi, g_w1T_hi); GETSYM(w1T_lo, g_w1T_lo);
    GETSYM(w2T_hi, g_w2T_hi); GETSYM(w2T_lo, g_w2T_lo);
    GETSYM(wlmT_hi, g_wlmT_hi); GETSYM(wlmT_lo, g_wlmT_lo);

    const int ROWS = BB * TT;
    const float scale = 0.125f;
    dim3 tb(32, 8);

    // ---- weight prep (per launch; deterministic) ----
    transpose_split<<<dim3(DD/32, DD/32, LL), tb>>>(wq, wqT_hi, wqT_lo, DD, DD);
    transpose_split<<<dim3(DD/32, DD/32, LL), tb>>>(wk, wkT_hi, wkT_lo, DD, DD);
    transpose_split<<<dim3(DD/32, DD/32, LL), tb>>>(wv, wvT_hi, wvT_lo, DD, DD);
    transpose_split<<<dim3(DD/32, DD/32, LL), tb>>>(wo, woT_hi, woT_lo, DD, DD);
    transpose_split<<<dim3(D4/32, DD/32, LL), tb>>>(w1, w1T_hi, w1T_lo, DD, D4);
    transpose_split<<<dim3(DD/32, D4/32, LL), tb>>>(w2, w2T_hi, w2T_lo, D4, DD);
    transpose_split<<<dim3(VV/32, DD/32, 1),  tb>>>(w_lm, wlmT_hi, wlmT_lo, DD, VV);

    embed_kernel<<<(BB*TT*DD + 255)/256, 256>>>(idx, tok, pos, x);

    dim3 gProj(DD/64,  ROWS/128);            // (12, 32)
    dim3 gMlp1(D4/64,  ROWS/128);            // (48, 32)
    dim3 gScr (TT/64,  TT/128, BB*HH);       // (16, 8, 48)
    dim3 gPV  (1,      TT/128, BB*HH);       // (1, 8, 48)
    dim3 gLM  (VV/64,  ROWS/128);            // (500, 32)

    const long long TTDD = (long long)TT*DD;
    const long long TT2  = (long long)TT*TT;

    for (int l = 0; l < LL; l++) {
        size_t wl  = (size_t)l*DD*DD;
        size_t w1l = (size_t)l*D4*DD;   // transposed [D4, DD]
        size_t w2l = (size_t)l*DD*D4;   // transposed [DD, D4]

        ln_planes<<<ROWS, 256>>>(x, h_hi, h_lo, ln1_g + l*DD, ln1_b + l*DD);

        // Q, K (planes out), V (transposed planes out)
        gemm_bf16<<<gProj, 256>>>(h_hi, h_lo, DD, 0, 0,
                                  wqT_hi + wl, wqT_lo + wl, DD, 0, 0,
                                  DD, 1.f, 0, 1,
                                  nullptr, 0, 0, 0,
                                  q_hi, q_lo, DD, 0, 0,
                                  nullptr, nullptr, 0, 0);
        gemm_bf16<<<gProj, 256>>>(h_hi, h_lo, DD, 0, 0,
                                  wkT_hi + wl, wkT_lo + wl, DD, 0, 0,
                                  DD, 1.f, 0, 1,
                                  nullptr, 0, 0, 0,
                                  k_hi, k_lo, DD, 0, 0,
                                  nullptr, nullptr, 0, 0);
        gemm_bf16<<<gProj, 256>>>(h_hi, h_lo, DD, 0, 0,
                                  wvT_hi + wl, wvT_lo + wl, DD, 0, 0,
                                  DD, 1.f, 0, 2,
                                  nullptr, 0, 0, 0,
                                  vT_hi, vT_lo, 0, 0, 0,
                                  nullptr, nullptr, 0, 0);

        // Scores: S = scale * Q_h @ K_h^T   z = b*HH + h
        gemm_bf16<<<gScr, 256>>>(q_hi, q_lo, DD, HD, TTDD,
                                 k_hi, k_lo, DD, HD, TTDD,
                                 HD, scale, HH, 0,
                                 s, TT, TT2, (long long)HH*TT2,
                                 nullptr, nullptr, 0, 0, 0,
                                 nullptr, nullptr, 0, 1 /*causal*/);

        softmax_planes<<<BB*HH*TT, 128>>>(s, p_hi, p_lo);

        // O = P @ V  (B = vT planes [HD, T] per head)
        gemm_bf16<<<gPV, 256>>>(p_hi, p_lo, TT, TT2, (long long)HH*TT2,
                                vT_hi, vT_lo, TT, (long long)HD*TT, (long long)DD*TT,
                                TT, 1.f, HH, 1,
                                nullptr, 0, 0, 0,
                                o_hi, o_lo, DD, HD, TTDD,
                                nullptr, nullptr, 0, 0);

        // x = x + O @ wo + bo
        gemm_bf16<<<gProj, 256>>>(o_hi, o_lo, DD, 0, 0,
                                  woT_hi + wl, woT_lo + wl, DD, 0, 0,
                                  DD, 1.f, 0, 0,
                                  x, DD, 0, 0,
                                  nullptr, nullptr, 0, 0, 0,
                                  bo + l*DD, x, 0, 0);

        // MLP
        ln_planes<<<ROWS, 256>>>(x, h_hi, h_lo, ln2_g + l*DD, ln2_b + l*DD);
        gemm_bf16<<<gMlp1, 256>>>(h_hi, h_lo, DD, 0, 0,
                                  w1T_hi + w1l, w1T_lo + w1l, DD, 0, 0,
                                  DD, 1.f, 0, 1,
                                  nullptr, 0, 0, 0,
                                  m_hi, m_lo, D4, 0, 0,
                                  b1 + (size_t)l*D4, nullptr, 1 /*relu*/, 0);
        gemm_bf16<<<gProj, 256>>>(m_hi, m_lo, D4, 0, 0,
                                  w2T_hi + w2l, w2T_lo + w2l, D4, 0, 0,
                                  D4, 1.f, 0, 0,
                                  x, DD, 0, 0,
                                  nullptr, nullptr, 0, 0, 0,
                                  b2 + l*DD, x, 0, 0);
    }

    // Final LN + LM head
    ln_planes<<<ROWS, 256>>>(x, h_hi, h_lo, lnf_g, lnf_b);
    gemm_bf16<<<gLM, 256>>>(h_hi, h_lo, DD, 0, 0,
                            wlmT_hi, wlmT_lo, DD, 0, 0,
                            DD, 1.f, 0, 0,
                            (float*)d_out, VV, 0, 0,
                            nullptr, nullptr, 0, 0, 0,
                            b_lm, nullptr, 0, 0);
}